// round 11
// baseline (speedup 1.0000x reference)
#include <cuda_runtime.h>
#include <cstdint>
#include <cstddef>

#define NB     32
#define NLAT   721
#define NLON   1440
#define NVEC   360          // NLON / 4
#define NWORDS 45           // NLON / 32
#define NUNITS 180          // NLON / 8 (one unit = one mask byte = 8 elements)
#define NTH    192          // 180 active unit-threads + 12 idle
#define NROWS  (NB * NLAT)  // 23072

// Skewed row: phys(j) = j + 4*(j>>5). Max 1439+4*44 = 1615 -> pad 1620.
#define SXSZ   1620
#define EIDX(j) ((j) + (((j) >> 5) << 2))

// Cross-CTA scratch (no allocations allowed).
__device__ int g_row_valid[NROWS];
__device__ int g_ticket = 0;

__device__ __forceinline__ bool nan_f(float x) {
    return (__float_as_uint(x) & 0x7FFFFFFFu) > 0x7F800000u;
}

__device__ __forceinline__ unsigned nib_of(float4 r) {
    return (unsigned)(!nan_f(r.x))        | ((unsigned)(!nan_f(r.y)) << 1)
         | ((unsigned)(!nan_f(r.z)) << 2) | ((unsigned)(!nan_f(r.w)) << 3);
}

// ---------------------------------------------------------------------------
// Single fused kernel: one 192-thread CTA per row, ONE 8-elem unit per thread.
// ---------------------------------------------------------------------------
__global__ void __launch_bounds__(NTH)
fill_kernel(const float4* __restrict__ sst4, const float* __restrict__ sst,
            float* __restrict__ out)
{
    __shared__ float    sx[SXSZ];       // skewed row
    __shared__ unsigned mask[NWORDS];   // bytes written per-unit, read as words
    __shared__ int4     wtab[NWORDS];   // {mask, prevOutside, nextOutside, 0}
    __shared__ int      s_is_last;

    unsigned char* maskb = (unsigned char*)mask;

    const int row  = blockIdx.x;        // b * NLAT + h
    const int t    = threadIdx.x;
    const int lane = t & 31;
    const int u    = t;                 // unit id (active if < NUNITS)
    const bool act = (u < NUNITS);

    const float4* __restrict__ src = sst4 + (size_t)row * NVEC;
    float4*       __restrict__ dst = (float4*)(out + (size_t)row * NLON);

    // ---- Loads: 2 independent LDG.128 per active thread ----
    float4 a0 = make_float4(0.f, 0.f, 0.f, 0.f), a1 = a0;
    if (act) { a0 = src[2 * u]; a1 = src[2 * u + 1]; }

    // ---- Skewed smem store + validity byte ----
    unsigned byte8 = 0u;
    if (act) {
        float4* sx4 = (float4*)sx;
        const int v0 = 2 * u, v1 = 2 * u + 1;
        sx4[v0 + (v0 >> 3)] = a0;
        sx4[v1 + (v1 >> 3)] = a1;
        byte8 = nib_of(a0) | (nib_of(a1) << 4);
        maskb[u] = (unsigned char)byte8;
    }
    __syncthreads();

    // ---- Word-validity bitmap B (redundant per warp: 2 ballots) ----
    const unsigned mwa = (lane < NWORDS)      ? mask[lane]      : 0u;
    const unsigned mwb = (lane + 32 < NWORDS) ? mask[lane + 32] : 0u;
    const unsigned bb1 = __ballot_sync(0xFFFFFFFFu, mwa != 0u);
    const unsigned bb2 = __ballot_sync(0xFFFFFFFFu, mwb != 0u);
    const unsigned long long B = ((unsigned long long)bb2 << 32) | bb1;
    const bool rv = (B != 0ull);

    if (t == 0) g_row_valid[row] = rv ? 1 : 0;

    // ---- Per-word packed table {mask, prev-outside, next-outside} ----
    if (rv && t < NWORDS) {
        const int fw = __ffsll((long long)B) - 1;
        const int firstv = (fw << 5) + __ffs(mask[fw]) - 1;
        const int lw = 63 - __clzll((long long)B);
        const int lastv  = (lw << 5) + 31 - __clz(mask[lw]);

        const unsigned long long lowB = B & ((1ull << t) - 1ull);
        int pv = lastv - NLON;                          // circular wrap
        if (lowB) {
            const int pw = 63 - __clzll((long long)lowB);
            pv = (pw << 5) + 31 - __clz(mask[pw]);
        }

        const unsigned long long highB = B >> (t + 1);
        int nv = firstv + NLON;                         // circular wrap
        if (highB) {
            const int nw = (t + 1) + __ffsll((long long)highB) - 1;
            nv = (nw << 5) + __ffs(mask[nw]) - 1;
        }
        wtab[t] = make_int4((int)mask[t], pv, nv, 0);
    }
    __syncthreads();

    // ---- Branch-free interpolation (8 elements, one unit) ----
    if (act) {
        if (rv) {
            const int w     = u >> 2;
            const int wbase = w << 5;
            const int bpos0 = (u & 3) << 3;             // 0,8,16,24
            const int4 wt   = wtab[w];                  // one LDS.128 (4-lane bcast)
            const unsigned cur = (unsigned)wt.x;

            // Boundary prev: largest valid strictly below bpos0 (else wt.y).
            const unsigned lomask = (1u << bpos0) - 1u; // bpos0=0 -> 0
            const unsigned lm = cur & lomask;
            const int prevB = lm ? (wbase + 31 - __clz(lm)) : wt.y;
            // Boundary next: smallest valid strictly above bpos0+7 (else wt.z).
            const unsigned hm = (cur >> (bpos0 + 7)) >> 1;
            const int nextB = hm ? (wbase + bpos0 + 7 + __ffs(hm)) : wt.z;

            // Wrap only for addressing; keep unwrapped for arithmetic.
            const int pmi = (prevB < 0)     ? prevB + NLON : prevB;
            const int nmi = (nextB >= NLON) ? nextB - NLON : nextB;
            const float spB = sx[EIDX(pmi)];
            const float snB = sx[EIDX(nmi)];

            const float fi0 = (float)(u << 3);
            const float fpB = (float)prevB;
            const float fnB = (float)nextB;

            const float RC[8] = {a0.x, a0.y, a0.z, a0.w, a1.x, a1.y, a1.z, a1.w};

            // Ascending prev chains (1 SEL each per element).
            float FP[8], Q[8];
            {
                float fpc = fpB, qc = spB;
                #pragma unroll
                for (int c = 0; c < 8; c++) {
                    const bool v = (byte8 >> c) & 1u;
                    fpc = v ? (fi0 + (float)c) : fpc;
                    qc  = v ? RC[c]            : qc;
                    FP[c] = fpc; Q[c] = qc;
                }
            }
            // Descending next chains.
            float FN[8], M[8];
            {
                float fnc = fnB, mc = snB;
                #pragma unroll
                for (int c = 7; c >= 0; c--) {
                    const bool v = (byte8 >> c) & 1u;
                    fnc = v ? (fi0 + (float)c) : fnc;
                    mc  = v ? RC[c]            : mc;
                    FN[c] = fnc; M[c] = mc;
                }
            }

            float res[8];
            #pragma unroll
            for (int c = 0; c < 8; c++) {
                // NaN elem: FP<FI<FN (dt>=2, exact small ints in float).
                // Valid elem: dt==0 -> 0*inf=NaN -> discarded by select.
                const float fic = fi0 + (float)c;
                const float dp  = fic - FP[c];
                const float dt  = FN[c] - FP[c];
                const float tt  = __fdividef(dp, dt);
                const float iv  = fmaf(tt, M[c] - Q[c], Q[c]);
                res[c] = ((byte8 >> c) & 1u) ? RC[c] : iv;
            }
            dst[2 * u]     = make_float4(res[0], res[1], res[2], res[3]);
            dst[2 * u + 1] = make_float4(res[4], res[5], res[6], res[7]);
        } else {
            dst[2 * u]     = a0;
            dst[2 * u + 1] = a1;
        }
    }

    // ---- Last-CTA polar fill (ticket pattern; graph-capturable) ----
    __threadfence();
    __syncthreads();
    if (t == 0) {
        const int ticket = atomicAdd(&g_ticket, 1);
        s_is_last = (ticket == (int)gridDim.x - 1) ? 1 : 0;
    }
    __syncthreads();
    if (!s_is_last) return;

    for (int b = 0; b < NB; b++) {
        int lr = NLAT - 1;
        while (lr >= 0 && !g_row_valid[b * NLAT + lr]) lr--;
        if (lr < 0 || lr == NLAT - 1) continue;         // common case

        const float* __restrict__ fill = out + ((size_t)b * NLAT + lr) * NLON;
        for (int h = lr + 1; h < NLAT; h++) {
            const float* __restrict__ sr   = sst + ((size_t)b * NLAT + h) * NLON;
            float*       __restrict__ orow = out + ((size_t)b * NLAT + h) * NLON;
            for (int i = t; i < NLON; i += NTH) {
                if (nan_f(sr[i])) orow[i] = fill[i];
            }
        }
    }
    if (t == 0) g_ticket = 0;                           // reset for next replay
}

// ---------------------------------------------------------------------------
extern "C" void kernel_launch(void* const* d_in, const int* in_sizes, int n_in,
                              void* d_out, int out_size)
{
    const float* sst = (const float*)d_in[0];
    float*       out = (float*)d_out;

    fill_kernel<<<NROWS, NTH>>>((const float4*)sst, sst, out);
}

// round 12
// speedup vs baseline: 1.0941x; 1.0941x over previous
#include <cuda_runtime.h>
#include <cstdint>
#include <cstddef>

#define NB     32
#define NLAT   721
#define NLON   1440
#define NVEC   360          // NLON / 4
#define NWORDS 45           // NLON / 32
#define NUNITS 180          // NLON / 8 (one unit = one mask byte = 8 elements)
#define NTH    96
#define NROWS  (NB * NLAT)  // 23072

// Skewed row: phys(j) = j + 4*(j>>5). Max 1439+4*44 = 1615 -> pad 1620.
#define SXSZ   1620
#define EIDX(j) ((j) + (((j) >> 5) << 2))

// Cross-CTA scratch (no allocations allowed).
__device__ int g_row_valid[NROWS];
__device__ int g_ticket = 0;

__device__ __forceinline__ bool nan_f(float x) {
    return (__float_as_uint(x) & 0x7FFFFFFFu) > 0x7F800000u;
}

__device__ __forceinline__ unsigned nib_of(float4 r) {
    return (unsigned)(!nan_f(r.x))        | ((unsigned)(!nan_f(r.y)) << 1)
         | ((unsigned)(!nan_f(r.z)) << 2) | ((unsigned)(!nan_f(r.w)) << 3);
}

// Boundary probe for unit u: prev/next valid index outside-or-at-edge of the
// unit, plus their (wrapped) skewed smem addresses. Pure ALU + 1 LDS.128.
struct Bnd { int prevB, nextB; float spB, snB; };

__device__ __forceinline__ Bnd probe(
    int u, const int4* __restrict__ wtab, const float* __restrict__ sx)
{
    const int w     = u >> 2;
    const int wbase = w << 5;
    const int bpos0 = (u & 3) << 3;                 // 0,8,16,24
    const int4 wt   = wtab[w];                      // LDS.128 (4-lane bcast)
    const unsigned cur = (unsigned)wt.x;

    const unsigned lomask = (1u << bpos0) - 1u;     // bpos0=0 -> 0
    const unsigned lm = cur & lomask;
    const int prevB = lm ? (wbase + 31 - __clz(lm)) : wt.y;
    const unsigned hm = (cur >> (bpos0 + 7)) >> 1;
    const int nextB = hm ? (wbase + bpos0 + 7 + __ffs(hm)) : wt.z;

    const int pmi = (prevB < 0)     ? prevB + NLON : prevB;
    const int nmi = (nextB >= NLON) ? nextB - NLON : nextB;
    Bnd b;
    b.prevB = prevB; b.nextB = nextB;
    b.spB = sx[EIDX(pmi)];
    b.snB = sx[EIDX(nmi)];
    return b;
}

// Arithmetic phase for one unit (no smem traffic).
__device__ __forceinline__ void finish_unit(
    int u, unsigned byte8, float4 rA, float4 rB, const Bnd& b,
    float4* __restrict__ dst)
{
    const float fi0 = (float)(u << 3);
    const float fpB = (float)b.prevB;
    const float fnB = (float)b.nextB;

    const float RC[8] = {rA.x, rA.y, rA.z, rA.w, rB.x, rB.y, rB.z, rB.w};

    float FP[8], Q[8];
    {
        float fpc = fpB, qc = b.spB;
        #pragma unroll
        for (int c = 0; c < 8; c++) {
            const bool v = (byte8 >> c) & 1u;
            fpc = v ? (fi0 + (float)c) : fpc;
            qc  = v ? RC[c]            : qc;
            FP[c] = fpc; Q[c] = qc;
        }
    }
    float FN[8], M[8];
    {
        float fnc = fnB, mc = b.snB;
        #pragma unroll
        for (int c = 7; c >= 0; c--) {
            const bool v = (byte8 >> c) & 1u;
            fnc = v ? (fi0 + (float)c) : fnc;
            mc  = v ? RC[c]            : mc;
            FN[c] = fnc; M[c] = mc;
        }
    }

    float res[8];
    #pragma unroll
    for (int c = 0; c < 8; c++) {
        // NaN elem: FP<FI<FN (dt>=2, exact small ints in float).
        // Valid elem: dt==0 -> 0*inf=NaN -> discarded by the select.
        const float fic = fi0 + (float)c;
        const float dp  = fic - FP[c];
        const float dt  = FN[c] - FP[c];
        const float tt  = __fdividef(dp, dt);
        const float iv  = fmaf(tt, M[c] - Q[c], Q[c]);
        res[c] = ((byte8 >> c) & 1u) ? RC[c] : iv;
    }
    dst[2 * u]     = make_float4(res[0], res[1], res[2], res[3]);
    dst[2 * u + 1] = make_float4(res[4], res[5], res[6], res[7]);
}

// ---------------------------------------------------------------------------
// Single fused kernel: one 96-thread CTA per row, TWO 8-elem units per thread,
// software-pipelined (both probes' LDS issued before either unit's math).
// ---------------------------------------------------------------------------
__global__ void __launch_bounds__(NTH, 16)
fill_kernel(const float4* __restrict__ sst4, const float* __restrict__ sst,
            float* __restrict__ out)
{
    __shared__ float    sx[SXSZ];       // skewed row
    __shared__ unsigned mask[NWORDS];   // bytes written per-unit, read as words
    __shared__ int4     wtab[NWORDS];   // {mask, prevOutside, nextOutside, 0}
    __shared__ int      s_is_last;

    unsigned char* maskb = (unsigned char*)mask;

    const int row  = blockIdx.x;        // b * NLAT + h
    const int t    = threadIdx.x;
    const int lane = t & 31;
    const int u1   = t;                 // units 0..95
    const int u2   = t + NTH;           // units 96..179 (t < 84)
    const bool has2 = (t < NUNITS - NTH);

    const float4* __restrict__ src = sst4 + (size_t)row * NVEC;
    float4*       __restrict__ dst = (float4*)(out + (size_t)row * NLON);

    // ---- Front-batched loads (4 independent LDG.128) ----
    float4 a0 = src[2 * u1];
    float4 a1 = src[2 * u1 + 1];
    float4 b0 = make_float4(0.f, 0.f, 0.f, 0.f), b1 = b0;
    if (has2) { b0 = src[2 * u2]; b1 = src[2 * u2 + 1]; }

    // ---- Skewed smem store (float4 idx: v + (v>>3)) ----
    float4* sx4 = (float4*)sx;
    {
        const int v0 = 2 * u1, v1 = 2 * u1 + 1;
        sx4[v0 + (v0 >> 3)] = a0;
        sx4[v1 + (v1 >> 3)] = a1;
        if (has2) {
            const int v2 = 2 * u2, v3 = 2 * u2 + 1;
            sx4[v2 + (v2 >> 3)] = b0;
            sx4[v3 + (v3 >> 3)] = b1;
        }
    }

    // ---- Validity byte per unit (mask bytes written directly) ----
    const unsigned byteA = nib_of(a0) | (nib_of(a1) << 4);
    const unsigned byteB = has2 ? (nib_of(b0) | (nib_of(b1) << 4)) : 0u;
    maskb[u1] = (unsigned char)byteA;
    if (has2) maskb[u2] = (unsigned char)byteB;
    __syncthreads();

    // ---- Word-validity bitmap B (redundant per warp: 2 ballots) ----
    const unsigned mwa = (lane < NWORDS)      ? mask[lane]      : 0u;
    const unsigned mwb = (lane + 32 < NWORDS) ? mask[lane + 32] : 0u;
    const unsigned bb1 = __ballot_sync(0xFFFFFFFFu, mwa != 0u);
    const unsigned bb2 = __ballot_sync(0xFFFFFFFFu, mwb != 0u);
    const unsigned long long B = ((unsigned long long)bb2 << 32) | bb1;
    const bool rv = (B != 0ull);

    if (t == 0) g_row_valid[row] = rv ? 1 : 0;

    // ---- Per-word packed table {mask, prev-outside, next-outside} ----
    if (rv && t < NWORDS) {
        const int fw = __ffsll((long long)B) - 1;
        const int firstv = (fw << 5) + __ffs(mask[fw]) - 1;
        const int lw = 63 - __clzll((long long)B);
        const int lastv  = (lw << 5) + 31 - __clz(mask[lw]);

        const unsigned long long lowB = B & ((1ull << t) - 1ull);
        int pv = lastv - NLON;                          // circular wrap
        if (lowB) {
            const int pw = 63 - __clzll((long long)lowB);
            pv = (pw << 5) + 31 - __clz(mask[pw]);
        }

        const unsigned long long highB = B >> (t + 1);
        int nv = firstv + NLON;                         // circular wrap
        if (highB) {
            const int nw = (t + 1) + __ffsll((long long)highB) - 1;
            nv = (nw << 5) + __ffs(mask[nw]) - 1;
        }
        wtab[t] = make_int4((int)mask[t], pv, nv, 0);
    }
    __syncthreads();

    // ---- Pipelined interpolation: probes (smem) first, math second ----
    if (rv) {
        const Bnd bA = probe(u1, wtab, sx);
        if (has2) {
            const Bnd bB = probe(u2, wtab, sx);         // LDS overlap with bA use
            finish_unit(u1, byteA, a0, a1, bA, dst);
            finish_unit(u2, byteB, b0, b1, bB, dst);
        } else {
            finish_unit(u1, byteA, a0, a1, bA, dst);
        }
    } else {
        dst[2 * u1]     = a0;
        dst[2 * u1 + 1] = a1;
        if (has2) { dst[2 * u2] = b0; dst[2 * u2 + 1] = b1; }
    }

    // ---- Last-CTA polar fill (ticket pattern; graph-capturable) ----
    __threadfence();
    __syncthreads();
    if (t == 0) {
        const int ticket = atomicAdd(&g_ticket, 1);
        s_is_last = (ticket == (int)gridDim.x - 1) ? 1 : 0;
    }
    __syncthreads();
    if (!s_is_last) return;

    for (int b = 0; b < NB; b++) {
        int lr = NLAT - 1;
        while (lr >= 0 && !g_row_valid[b * NLAT + lr]) lr--;
        if (lr < 0 || lr == NLAT - 1) continue;         // common case

        const float* __restrict__ fill = out + ((size_t)b * NLAT + lr) * NLON;
        for (int h = lr + 1; h < NLAT; h++) {
            const float* __restrict__ sr   = sst + ((size_t)b * NLAT + h) * NLON;
            float*       __restrict__ orow = out + ((size_t)b * NLAT + h) * NLON;
            for (int i = t; i < NLON; i += NTH) {
                if (nan_f(sr[i])) orow[i] = fill[i];
            }
        }
    }
    if (t == 0) g_ticket = 0;                           // reset for next replay
}

// ---------------------------------------------------------------------------
extern "C" void kernel_launch(void* const* d_in, const int* in_sizes, int n_in,
                              void* d_out, int out_size)
{
    const float* sst = (const float*)d_in[0];
    float*       out = (float*)d_out;

    fill_kernel<<<NROWS, NTH>>>((const float4*)sst, sst, out);
}

// round 13
// speedup vs baseline: 1.5616x; 1.4273x over previous
#include <cuda_runtime.h>
#include <cstdint>
#include <cstddef>

#define NB     32
#define NLAT   721
#define NLON   1440
#define NVEC   360          // NLON / 4
#define NWORDS 45           // NLON / 32
#define NUNITS 180          // NLON / 8 (one unit = one mask byte = 8 elements)
#define NTH    96
#define NROWS  (NB * NLAT)  // 23072

// Skewed row: phys(j) = j + 4*(j>>5). Max 1439+4*44 = 1615 -> pad 1620.
#define SXSZ   1620
#define EIDX(j) ((j) + (((j) >> 5) << 2))

// Cross-kernel scratch (no allocations allowed).
__device__ int g_row_valid[NROWS];

__device__ __forceinline__ bool nan_f(float x) {
    return (__float_as_uint(x) & 0x7FFFFFFFu) > 0x7F800000u;
}

__device__ __forceinline__ unsigned nib_of(float4 r) {
    return (unsigned)(!nan_f(r.x))        | ((unsigned)(!nan_f(r.y)) << 1)
         | ((unsigned)(!nan_f(r.z)) << 2) | ((unsigned)(!nan_f(r.w)) << 3);
}

// ---------------------------------------------------------------------------
// Per-unit (8 contiguous elements) branch-free interpolation.
// ---------------------------------------------------------------------------
__device__ __forceinline__ void do_unit(
    int u, unsigned byte8, float4 rA, float4 rB,
    const float* __restrict__ sx, const int4* __restrict__ wtab,
    float4* __restrict__ dst)
{
    const int w     = u >> 2;
    const int wbase = w << 5;
    const int bpos0 = (u & 3) << 3;                 // 0,8,16,24
    const int4 wt   = wtab[w];                      // one LDS.128 (4-lane bcast)
    const unsigned cur = (unsigned)wt.x;

    // Boundary prev: largest valid strictly below bpos0 (else wt.y).
    const unsigned lomask = (1u << bpos0) - 1u;     // bpos0=0 -> 0
    const unsigned lm = cur & lomask;
    const int prevB = lm ? (wbase + 31 - __clz(lm)) : wt.y;
    // Boundary next: smallest valid strictly above bpos0+7 (else wt.z).
    const unsigned hm = (cur >> (bpos0 + 7)) >> 1;
    const int nextB = hm ? (wbase + bpos0 + 7 + __ffs(hm)) : wt.z;

    // Wrap only for addressing (values); keep unwrapped for arithmetic.
    const int pmi = (prevB < 0)      ? prevB + NLON : prevB;
    const int nmi = (nextB >= NLON)  ? nextB - NLON : nextB;
    const float spB = sx[EIDX(pmi)];
    const float snB = sx[EIDX(nmi)];

    const float fi0 = (float)(u << 3);
    const float fpB = (float)prevB;
    const float fnB = (float)nextB;

    const float RC[8] = {rA.x, rA.y, rA.z, rA.w, rB.x, rB.y, rB.z, rB.w};

    // Ascending prev-index/value chains (1 SEL each per element).
    float FP[8], Q[8];
    {
        float fpc = fpB, qc = spB;
        #pragma unroll
        for (int c = 0; c < 8; c++) {
            const bool v = (byte8 >> c) & 1u;
            fpc = v ? (fi0 + (float)c) : fpc;
            qc  = v ? RC[c]            : qc;
            FP[c] = fpc; Q[c] = qc;
        }
    }
    // Descending next-index/value chains.
    float FN[8], M[8];
    {
        float fnc = fnB, mc = snB;
        #pragma unroll
        for (int c = 7; c >= 0; c--) {
            const bool v = (byte8 >> c) & 1u;
            fnc = v ? (fi0 + (float)c) : fnc;
            mc  = v ? RC[c]            : mc;
            FN[c] = fnc; M[c] = mc;
        }
    }

    float res[8];
    #pragma unroll
    for (int c = 0; c < 8; c++) {
        // NaN element: FP < FI < FN (dt >= 2, exact small ints in float).
        // Valid element: dt==0 -> 0*inf=NaN -> discarded by the select.
        const float fic = fi0 + (float)c;
        const float dp  = fic - FP[c];
        const float dt  = FN[c] - FP[c];
        const float tt  = __fdividef(dp, dt);
        const float iv  = fmaf(tt, M[c] - Q[c], Q[c]);
        res[c] = ((byte8 >> c) & 1u) ? RC[c] : iv;
    }
    dst[2 * u]     = make_float4(res[0], res[1], res[2], res[3]);
    dst[2 * u + 1] = make_float4(res[4], res[5], res[6], res[7]);
}

// ---------------------------------------------------------------------------
// Hot kernel: one 96-thread CTA per row, TWO units per thread (R10 shape).
// NO fence / ticket / atomic tail -- cross-CTA visibility comes from the
// kernel boundary before fill_polar_kernel.
// ---------------------------------------------------------------------------
__global__ void __launch_bounds__(NTH)
fill_rows_kernel(const float4* __restrict__ sst4, float* __restrict__ out)
{
    __shared__ float    sx[SXSZ];       // skewed row
    __shared__ unsigned mask[NWORDS];   // bytes written per-unit, read as words
    __shared__ int4     wtab[NWORDS];   // {mask, prevOutside, nextOutside, 0}

    unsigned char* maskb = (unsigned char*)mask;

    const int row  = blockIdx.x;        // b * NLAT + h
    const int t    = threadIdx.x;
    const int lane = t & 31;
    const int u1   = t;                 // units 0..95
    const int u2   = t + NTH;           // units 96..179 (t < 84)
    const bool has2 = (t < NUNITS - NTH);

    const float4* __restrict__ src = sst4 + (size_t)row * NVEC;
    float4*       __restrict__ dst = (float4*)(out + (size_t)row * NLON);

    // ---- Front-batched loads (4 independent LDG.128) ----
    float4 a0 = src[2 * u1];
    float4 a1 = src[2 * u1 + 1];
    float4 b0 = make_float4(0.f, 0.f, 0.f, 0.f), b1 = b0;
    if (has2) { b0 = src[2 * u2]; b1 = src[2 * u2 + 1]; }

    // ---- Skewed smem store (float4 idx: v + (v>>3)) ----
    float4* sx4 = (float4*)sx;
    {
        const int v0 = 2 * u1, v1 = 2 * u1 + 1;
        sx4[v0 + (v0 >> 3)] = a0;
        sx4[v1 + (v1 >> 3)] = a1;
        if (has2) {
            const int v2 = 2 * u2, v3 = 2 * u2 + 1;
            sx4[v2 + (v2 >> 3)] = b0;
            sx4[v3 + (v3 >> 3)] = b1;
        }
    }

    // ---- Validity byte per unit (mask bytes written directly) ----
    const unsigned byteA = nib_of(a0) | (nib_of(a1) << 4);
    const unsigned byteB = has2 ? (nib_of(b0) | (nib_of(b1) << 4)) : 0u;
    maskb[u1] = (unsigned char)byteA;
    if (has2) maskb[u2] = (unsigned char)byteB;
    __syncthreads();

    // ---- Word-validity bitmap B (redundant per warp: 2 ballots) ----
    const unsigned mwa = (lane < NWORDS)      ? mask[lane]      : 0u;
    const unsigned mwb = (lane + 32 < NWORDS) ? mask[lane + 32] : 0u;
    const unsigned bb1 = __ballot_sync(0xFFFFFFFFu, mwa != 0u);
    const unsigned bb2 = __ballot_sync(0xFFFFFFFFu, mwb != 0u);
    const unsigned long long B = ((unsigned long long)bb2 << 32) | bb1;
    const bool rv = (B != 0ull);

    if (t == 0) g_row_valid[row] = rv ? 1 : 0;

    // ---- Per-word packed table {mask, prev-outside, next-outside} ----
    if (rv && t < NWORDS) {
        const int fw = __ffsll((long long)B) - 1;
        const int firstv = (fw << 5) + __ffs(mask[fw]) - 1;
        const int lw = 63 - __clzll((long long)B);
        const int lastv  = (lw << 5) + 31 - __clz(mask[lw]);

        const unsigned long long lowB = B & ((1ull << t) - 1ull);
        int pv = lastv - NLON;                          // circular wrap
        if (lowB) {
            const int pw = 63 - __clzll((long long)lowB);
            pv = (pw << 5) + 31 - __clz(mask[pw]);
        }

        const unsigned long long highB = B >> (t + 1);
        int nv = firstv + NLON;                         // circular wrap
        if (highB) {
            const int nw = (t + 1) + __ffsll((long long)highB) - 1;
            nv = (nw << 5) + __ffs(mask[nw]) - 1;
        }
        wtab[t] = make_int4((int)mask[t], pv, nv, 0);
    }
    __syncthreads();

    // ---- Branch-free interpolation (8 elements per unit) ----
    if (rv) {
        do_unit(u1, byteA, a0, a1, sx, wtab, dst);
        if (has2) do_unit(u2, byteB, b0, b1, sx, wtab, dst);
    } else {
        dst[2 * u1]     = a0;
        dst[2 * u1 + 1] = a1;
        if (has2) { dst[2 * u2] = b0; dst[2 * u2 + 1] = b1; }
    }
}

// ---------------------------------------------------------------------------
// Polar kernel: one CTA per batch; immediate exit in the common case
// (lastrow == NLAT-1). Kernel boundary guarantees rows/out visibility.
// ---------------------------------------------------------------------------
__global__ void __launch_bounds__(256)
fill_polar_kernel(const float* __restrict__ sst, float* __restrict__ out)
{
    const int b   = blockIdx.x;
    const int tid = threadIdx.x;

    __shared__ int s_lastrow;
    if (tid == 0) s_lastrow = -1;
    __syncthreads();

    int loc = -1;
    for (int h = tid; h < NLAT; h += 256)
        if (g_row_valid[b * NLAT + h]) loc = (h > loc) ? h : loc;
    if (loc >= 0) atomicMax(&s_lastrow, loc);
    __syncthreads();

    const int lastrow = s_lastrow;
    if (lastrow < 0 || lastrow >= NLAT - 1) return;     // common case

    // Fill value row: out[b, lastrow, :] equals the reference's v there.
    const float* __restrict__ fill = out + ((size_t)b * NLAT + lastrow) * NLON;
    for (int h = lastrow + 1; h < NLAT; h++) {
        const float* __restrict__ sr   = sst + ((size_t)b * NLAT + h) * NLON;
        float*       __restrict__ orow = out + ((size_t)b * NLAT + h) * NLON;
        for (int i = tid; i < NLON; i += 256) {
            if (nan_f(sr[i])) orow[i] = fill[i];
        }
    }
}

// ---------------------------------------------------------------------------
extern "C" void kernel_launch(void* const* d_in, const int* in_sizes, int n_in,
                              void* d_out, int out_size)
{
    const float* sst = (const float*)d_in[0];
    float*       out = (float*)d_out;

    fill_rows_kernel<<<NROWS, NTH>>>((const float4*)sst, out);
    fill_polar_kernel<<<NB, 256>>>(sst, out);
}